// round 7
// baseline (speedup 1.0000x reference)
#include <cuda_runtime.h>
#include <cstdint>

// Fused: conv3x3 (zero-pad bottom/right) -> +bias -> *scale -> maxpool2x2 -> clamp[0,1]
// x: [B,3,512,512] f32, w: [16,3,3,3], bias: [16], scale: [16,1,1]
// out: [B,16,256,256] f32
//
// One thread = 1x2 vertical pair of pooled pixels for 4 OC, packed f32x2 FMA.
// R6 rewrite: single base pointer + immediate-offset LDGs, zero-padding via
// base-pointer select into a static zero array (no per-load predication),
// LDS.128 weight loads, first-tap mul (no acc zero-init).

typedef unsigned long long ull;

#define OCN 16
#define OCG 4
#define ICN 3
#define IH 512
#define IW 512
#define PH 256
#define PW 256
#define CH (IH * IW)

// Zero-filled padding source: large enough for any (ic, row) immediate offset
// (max 2*CH + 5*IW + 2 floats). Static __device__ arrays are zero-initialized.
__device__ float g_zpad[2 * CH + 6 * IW + 8];

__device__ __forceinline__ ull pack2(float a, float b) {
    ull r;
    asm("mov.b64 %0, {%1, %2};" : "=l"(r) : "f"(a), "f"(b));
    return r;
}
__device__ __forceinline__ void unpack2(ull p, float& a, float& b) {
    asm("mov.b64 {%0, %1}, %2;" : "=f"(a), "=f"(b) : "l"(p));
}
// {hi(lo-pair), lo(hi-pair)} — the straddling middle column pair.
__device__ __forceinline__ ull midpair(ull lo, ull hi) {
    ull r;
    asm("{\n\t"
        ".reg .b32 a, b, c, d;\n\t"
        "mov.b64 {a, b}, %1;\n\t"
        "mov.b64 {c, d}, %2;\n\t"
        "mov.b64 %0, {b, c};\n\t"
        "}" : "=l"(r) : "l"(lo), "l"(hi));
    return r;
}
__device__ __forceinline__ void fma2(ull& acc, ull a, ull b) {
    asm("fma.rn.f32x2 %0, %1, %2, %0;" : "+l"(acc) : "l"(a), "l"(b));
}
__device__ __forceinline__ ull mul2(ull a, ull b) {
    ull d;
    asm("mul.rn.f32x2 %0, %1, %2;" : "=l"(d) : "l"(a), "l"(b));
    return d;
}
__device__ __forceinline__ ull fma2n(ull a, ull b, ull c) {
    ull d;
    asm("fma.rn.f32x2 %0, %1, %2, %3;" : "=l"(d) : "l"(a), "l"(b), "l"(c));
    return d;
}

__global__ __launch_bounds__(128, 6)
void conv_pool_clamp_kernel(const float* __restrict__ x,
                            const float* __restrict__ w,
                            const float* __restrict__ bias,
                            const float* __restrict__ scale,
                            float* __restrict__ out) {
    // Weights {w,w} in 10-ull groups (80B, 16B-aligned) for LDS.128 pair loads.
    __shared__ __align__(16) ull sw[ICN * OCG * 10];
    __shared__ ull ssc[OCG];   // {s, s}
    __shared__ ull sbs[OCG];   // {b*s, b*s}

    const int tid = threadIdx.x;
    const int bx  = blockIdx.x;               // bit0 = pw half, bits[2:1] = oc group
    const int ocbase = (bx >> 1) * OCG;

    for (int i = tid; i < ICN * OCG * 9; i += 128) {
        const int g = i / 9, t = i % 9;
        const int ic = g / OCG, oc = g % OCG;
        float v = w[((ocbase + oc) * ICN + ic) * 9 + t];
        sw[g * 10 + t] = pack2(v, v);
    }
    if (tid < OCG) {
        float s  = scale[ocbase + tid];
        float bs = bias[ocbase + tid] * s;
        ssc[tid] = pack2(s, s);
        sbs[tid] = pack2(bs, bs);
    }
    __syncthreads();

    const int pw  = (bx & 1) * 128 + tid;     // 0..255
    const int phb = blockIdx.y;               // 0..127 : pooled-row PAIR index
    const int bi  = blockIdx.z;               // 0..B-1
    const int ih0 = phb * 4;                  // first input row of the 6-row patch

    // Base pointers; all loads below are [base + compile-time-imm].
    const float* base = x + (size_t)bi * (ICN * CH) + ih0 * IW + pw * 2;
    const float* hb   = (pw != PW - 1) ? (base + 2) : g_zpad;   // hi pair source
    const bool bot_ok = (ih0 + 4 < IH);                          // rows 4,5 valid?
    const float* lb45 = bot_ok ? base : g_zpad;
    const float* hb45 = bot_ok ? hb   : g_zpad;

    // acc[oc][cr]: conv output row (4*phb + cr), columns {2pw,2pw+1} packed.
    ull acc[OCG][4];

#pragma unroll
    for (int ic = 0; ic < ICN; ic++) {
        // 6x4 patch as overlapping column pairs; rows 4,5 / right edge read
        // from the zero pad via the preselected bases (no predication).
        ull p[6][3];
#pragma unroll
        for (int rr = 0; rr < 6; rr++) {
            const float* lp = (rr < 4) ? base : lb45;
            const float* hp = (rr < 4) ? hb   : hb45;
            ull lo = *(const ull*)(lp + ic * CH + rr * IW);       // {c0, c1}
            ull hi = *(const ull*)(hp + ic * CH + rr * IW);       // {c2, c3}
            p[rr][0] = lo;
            p[rr][1] = midpair(lo, hi);                           // {c1, c2}
            p[rr][2] = hi;
        }

#pragma unroll
        for (int oc = 0; oc < OCG; oc++) {
            const ull* wg = &sw[(ic * OCG + oc) * 10];
            ulonglong2 wA = *(const ulonglong2*)(wg + 0);   // taps 0,1
            ulonglong2 wB = *(const ulonglong2*)(wg + 2);   // taps 2,3
            ulonglong2 wC = *(const ulonglong2*)(wg + 4);   // taps 4,5
            ulonglong2 wD = *(const ulonglong2*)(wg + 6);   // taps 6,7
            ull w8 = wg[8];
            const ull wt[9] = {wA.x, wA.y, wB.x, wB.y, wC.x, wC.y, wD.x, wD.y, w8};

#pragma unroll
            for (int kh = 0; kh < 3; kh++) {
#pragma unroll
                for (int kw = 0; kw < 3; kw++) {
                    const ull w2 = wt[kh * 3 + kw];
                    if (ic == 0 && kh == 0 && kw == 0) {
                        // first tap: plain mul (skips acc zero-init)
                        acc[oc][0] = mul2(p[0][kw], w2);
                        acc[oc][1] = mul2(p[1][kw], w2);
                        acc[oc][2] = mul2(p[2][kw], w2);
                        acc[oc][3] = mul2(p[3][kw], w2);
                    } else {
                        fma2(acc[oc][0], p[kh + 0][kw], w2);
                        fma2(acc[oc][1], p[kh + 1][kw], w2);
                        fma2(acc[oc][2], p[kh + 2][kw], w2);
                        fma2(acc[oc][3], p[kh + 3][kw], w2);
                    }
                }
            }
        }
    }

    // Epilogue: (y + bias) * scale -> max over 2x2 -> clamp [0,1]; two pooled rows.
    const int ph0 = phb * 2;
    float* ob = out + (((size_t)(bi * OCN + ocbase)) * PH + ph0) * PW + pw;
#pragma unroll
    for (int oc = 0; oc < OCG; oc++) {
        float v0, v1, v2, v3;
        ull t = fma2n(acc[oc][0], ssc[oc], sbs[oc]);
        ull b = fma2n(acc[oc][1], ssc[oc], sbs[oc]);
        unpack2(t, v0, v1); unpack2(b, v2, v3);
        float m0 = fminf(fmaxf(fmaxf(fmaxf(v0, v1), fmaxf(v2, v3)), 0.0f), 1.0f);

        t = fma2n(acc[oc][2], ssc[oc], sbs[oc]);
        b = fma2n(acc[oc][3], ssc[oc], sbs[oc]);
        unpack2(t, v0, v1); unpack2(b, v2, v3);
        float m1 = fminf(fmaxf(fmaxf(fmaxf(v0, v1), fmaxf(v2, v3)), 0.0f), 1.0f);

        float* oc_ptr = ob + (size_t)oc * (PH * PW);
        oc_ptr[0]  = m0;
        oc_ptr[PW] = m1;
    }
}

extern "C" void kernel_launch(void* const* d_in, const int* in_sizes, int n_in,
                              void* d_out, int out_size) {
    const float* x     = (const float*)d_in[0];
    const float* w     = (const float*)d_in[1];
    const float* bias  = (const float*)d_in[2];
    const float* scale = (const float*)d_in[3];
    float* out = (float*)d_out;

    const int B = in_sizes[0] / (ICN * IH * IW);   // 32

    dim3 block(128);
    dim3 grid(8, PH / 2, B);   // x: {pw half} x {4 oc groups}, y: pooled-row pair, z: batch
    conv_pool_clamp_kernel<<<grid, block>>>(x, w, bias, scale, out);
}

// round 8
// speedup vs baseline: 1.0081x; 1.0081x over previous
#include <cuda_runtime.h>
#include <cstdint>

// Fused: conv3x3 (zero-pad bottom/right) -> +bias -> *scale -> maxpool2x2 -> clamp[0,1]
// x: [B,3,512,512] f32, w: [16,3,3,3], bias: [16], scale: [16,1,1]
// out: [B,16,256,256] f32
//
// One thread = 1x2 vertical pair of pooled pixels for 4 OC, packed f32x2 FMA.
// R7: weights/scale/bias moved to __constant__ memory ({w,w} pre-duplicated by a
// prep kernel + cudaMemcpyToSymbolAsync). Constant loads become LDCU -> uniform
// regs; FFMA2 with a UR operand sidesteps the 3-bank RF conflict (rt 3 -> 2)
// and all weight LDS + smem setup disappear.

typedef unsigned long long ull;

#define OCN 16
#define OCG 4
#define ICN 3
#define IH 512
#define IW 512
#define PH 256
#define PW 256
#define NW (OCN * ICN * 9)   // 432 weight taps

struct Params {
    ull w2[NW];    // {w, w}
    ull sc[OCN];   // {s, s}
    ull bs[OCN];   // {b*s, b*s}
};

__device__    Params g_stage;   // written by prep kernel
__constant__  Params c_p;       // copied from g_stage each launch (D2D memcpy node)

__device__ __forceinline__ ull pack2(float a, float b) {
    ull r;
    asm("mov.b64 %0, {%1, %2};" : "=l"(r) : "f"(a), "f"(b));
    return r;
}
__device__ __forceinline__ void unpack2(ull p, float& a, float& b) {
    asm("mov.b64 {%0, %1}, %2;" : "=f"(a), "=f"(b) : "l"(p));
}
// {hi(lo-pair), lo(hi-pair)} — the straddling middle column pair.
__device__ __forceinline__ ull midpair(ull lo, ull hi) {
    ull r;
    asm("{\n\t"
        ".reg .b32 a, b, c, d;\n\t"
        "mov.b64 {a, b}, %1;\n\t"
        "mov.b64 {c, d}, %2;\n\t"
        "mov.b64 %0, {b, c};\n\t"
        "}" : "=l"(r) : "l"(lo), "l"(hi));
    return r;
}
__device__ __forceinline__ void fma2(ull& acc, ull a, ull b) {
    asm("fma.rn.f32x2 %0, %1, %2, %0;" : "+l"(acc) : "l"(a), "l"(b));
}
__device__ __forceinline__ ull fma2n(ull a, ull b, ull c) {
    ull d;
    asm("fma.rn.f32x2 %0, %1, %2, %3;" : "=l"(d) : "l"(a), "l"(b), "l"(c));
    return d;
}

__global__ void prep_kernel(const float* __restrict__ w,
                            const float* __restrict__ bias,
                            const float* __restrict__ scale) {
    const int i = threadIdx.x;
    if (i < NW) {
        float v = w[i];
        g_stage.w2[i] = pack2(v, v);
    }
    if (i < OCN) {
        float s  = scale[i];
        float bs = bias[i] * s;
        g_stage.sc[i] = pack2(s, s);
        g_stage.bs[i] = pack2(bs, bs);
    }
}

__global__ __launch_bounds__(128, 6)
void conv_pool_clamp_kernel(const float* __restrict__ x,
                            float* __restrict__ out) {
    const int tid = threadIdx.x;
    const int bx  = blockIdx.x;               // bit0 = pw half, bits[2:1] = oc group
    const int ocbase = (bx >> 1) * OCG;

    const int pw  = (bx & 1) * 128 + tid;     // 0..255
    const int phb = blockIdx.y;               // 0..127 : pooled-row PAIR index
    const int bi  = blockIdx.z;               // 0..B-1

    const int ih0 = phb * 4;                  // first input row of the 6-row patch
    const int iw0 = pw * 2;

    // acc[oc][cr]: conv output row (4*phb + cr), columns {2pw,2pw+1} packed.
    ull acc[OCG][4];
#pragma unroll
    for (int o = 0; o < OCG; o++)
#pragma unroll
        for (int c = 0; c < 4; c++) acc[o][c] = 0ull;

#pragma unroll
    for (int ic = 0; ic < ICN; ic++) {
        const float* xc = x + ((size_t)bi * ICN + ic) * (IH * IW);

        // 6x4 patch as overlapping column pairs. Aligned pairs load directly
        // as 64-bit words (iw0 even -> 8B aligned); only the middle pair is built.
        ull p[6][3];
#pragma unroll
        for (int rr = 0; rr < 6; rr++) {
            ull lo = 0ull, hi = 0ull;
            const int ih = ih0 + rr;
            if (ih < IH) {
                const float* row = xc + (size_t)ih * IW + iw0;
                lo = *(const ull*)row;                          // {c0, c1}
                if (iw0 + 2 < IW) hi = *(const ull*)(row + 2);  // {c2, c3}
            }
            p[rr][0] = lo;
            p[rr][1] = midpair(lo, hi);                         // {c1, c2}
            p[rr][2] = hi;
        }

#pragma unroll
        for (int oc = 0; oc < OCG; oc++) {
            // Constant-space weight group; offsets are (UR-uniform base + imm)
            // after full unroll -> LDCU, weights live in uniform registers.
            const ull* wp = &c_p.w2[((ocbase + oc) * ICN + ic) * 9];
#pragma unroll
            for (int kh = 0; kh < 3; kh++) {
#pragma unroll
                for (int kw = 0; kw < 3; kw++) {
                    const ull w2 = wp[kh * 3 + kw];
                    fma2(acc[oc][0], p[kh + 0][kw], w2);
                    fma2(acc[oc][1], p[kh + 1][kw], w2);
                    fma2(acc[oc][2], p[kh + 2][kw], w2);
                    fma2(acc[oc][3], p[kh + 3][kw], w2);
                }
            }
        }
    }

    // Epilogue: (y + bias) * scale -> max over 2x2 -> clamp [0,1]; two pooled rows.
    const int ph0 = phb * 2;
    float* ob = out + (((size_t)(bi * OCN + ocbase)) * PH + ph0) * PW + pw;
#pragma unroll
    for (int oc = 0; oc < OCG; oc++) {
        const ull sc = c_p.sc[ocbase + oc];
        const ull bs = c_p.bs[ocbase + oc];
        float v0, v1, v2, v3;
        ull t = fma2n(acc[oc][0], sc, bs);
        ull b = fma2n(acc[oc][1], sc, bs);
        unpack2(t, v0, v1); unpack2(b, v2, v3);
        float m0 = fminf(fmaxf(fmaxf(fmaxf(v0, v1), fmaxf(v2, v3)), 0.0f), 1.0f);

        t = fma2n(acc[oc][2], sc, bs);
        b = fma2n(acc[oc][3], sc, bs);
        unpack2(t, v0, v1); unpack2(b, v2, v3);
        float m1 = fminf(fmaxf(fmaxf(fmaxf(v0, v1), fmaxf(v2, v3)), 0.0f), 1.0f);

        float* oc_ptr = ob + (size_t)oc * (PH * PW);
        oc_ptr[0]  = m0;
        oc_ptr[PW] = m1;
    }
}

extern "C" void kernel_launch(void* const* d_in, const int* in_sizes, int n_in,
                              void* d_out, int out_size) {
    const float* x     = (const float*)d_in[0];
    const float* w     = (const float*)d_in[1];
    const float* bias  = (const float*)d_in[2];
    const float* scale = (const float*)d_in[3];
    float* out = (float*)d_out;

    const int B = in_sizes[0] / (ICN * IH * IW);   // 32

    // 1) pack {w,w} pairs into device staging
    prep_kernel<<<1, 512>>>(w, bias, scale);

    // 2) staging -> __constant__ (D2D async memcpy: graph-capturable node)
    void* stage_ptr = nullptr;
    cudaGetSymbolAddress(&stage_ptr, g_stage);
    cudaMemcpyToSymbolAsync(c_p, stage_ptr, sizeof(Params), 0,
                            cudaMemcpyDeviceToDevice, 0);

    // 3) main kernel
    dim3 block(128);
    dim3 grid(8, PH / 2, B);   // x: {pw half} x {4 oc groups}, y: pooled-row pair, z: batch
    conv_pool_clamp_kernel<<<grid, block>>>(x, out);
}

// round 9
// speedup vs baseline: 1.0297x; 1.0214x over previous
#include <cuda_runtime.h>
#include <cstdint>

// Fused: conv3x3 (zero-pad bottom/right) -> +bias -> *scale -> maxpool2x2 -> clamp[0,1]
// x: [B,3,512,512] f32, w: [16,3,3,3], bias: [16], scale: [16,1,1]
// out: [B,16,256,256] f32
//
// R9: thread tile widened to 4 output cols (2 pooled cols) x 4 conv rows x 2 OC.
// Each constant weight load now feeds 8 FFMA2 (was 4) -> the 108-load weight
// stream (R8's hidden co-binder, LDC floor 8) halves to 54. LDG per output /4.
// Coalesced STG.64 epilogue. Weights {w,w} in __constant__ via prep kernel.

typedef unsigned long long ull;

#define OCN 16
#define OCG 2
#define ICN 3
#define IH 512
#define IW 512
#define PH 256
#define PW 256
#define CH (IH * IW)
#define NW (OCN * ICN * 9)   // 432 weight taps

struct Params {
    ull w2[NW];    // {w, w}
    ull sc[OCN];   // {s, s}
    ull bs[OCN];   // {b*s, b*s}
};

__device__    Params g_stage;   // written by prep kernel
__constant__  Params c_p;       // copied from g_stage (D2D memcpy node)

// Zero-filled pad source for bottom/right edges; offsets go up to 2*CH+5*IW+6.
__device__ float g_zpad[2 * CH + 6 * IW + 8];

__device__ __forceinline__ ull pack2(float a, float b) {
    ull r;
    asm("mov.b64 %0, {%1, %2};" : "=l"(r) : "f"(a), "f"(b));
    return r;
}
__device__ __forceinline__ void unpack2(ull p, float& a, float& b) {
    asm("mov.b64 {%0, %1}, %2;" : "=f"(a), "=f"(b) : "l"(p));
}
// {hi(lo-pair), lo(hi-pair)} — straddling middle column pair.
__device__ __forceinline__ ull midpair(ull lo, ull hi) {
    ull r;
    asm("{\n\t"
        ".reg .b32 a, b, c, d;\n\t"
        "mov.b64 {a, b}, %1;\n\t"
        "mov.b64 {c, d}, %2;\n\t"
        "mov.b64 %0, {b, c};\n\t"
        "}" : "=l"(r) : "l"(lo), "l"(hi));
    return r;
}
__device__ __forceinline__ void fma2(ull& acc, ull a, ull b) {
    asm("fma.rn.f32x2 %0, %1, %2, %0;" : "+l"(acc) : "l"(a), "l"(b));
}
__device__ __forceinline__ ull fma2n(ull a, ull b, ull c) {
    ull d;
    asm("fma.rn.f32x2 %0, %1, %2, %3;" : "=l"(d) : "l"(a), "l"(b), "l"(c));
    return d;
}

__global__ void prep_kernel(const float* __restrict__ w,
                            const float* __restrict__ bias,
                            const float* __restrict__ scale) {
    const int i = threadIdx.x;
    if (i < NW) {
        float v = w[i];
        g_stage.w2[i] = pack2(v, v);
    }
    if (i < OCN) {
        float s  = scale[i];
        float bs = bias[i] * s;
        g_stage.sc[i] = pack2(s, s);
        g_stage.bs[i] = pack2(bs, bs);
    }
}

__global__ __launch_bounds__(128, 5)
void conv_pool_clamp_kernel(const float* __restrict__ x,
                            float* __restrict__ out) {
    const int tid = threadIdx.x;              // 0..127: pooled cols {2t, 2t+1}
    const int ocbase = blockIdx.x * OCG;      // 0,2,..,14
    const int phb = blockIdx.y;               // 0..127: pooled-row pair
    const int bi  = blockIdx.z;

    const int ih0 = phb * 4;                  // 6-row input patch start
    const int iw0 = tid * 4;                  // 6-col input patch start

    // Base pointers (all loads are base + compile-time imm). Edge handling via
    // base select into the static zero array -> no per-load predication.
    const float* base = x + (size_t)bi * (ICN * CH) + ih0 * IW + iw0;
    const bool  redge = (tid == 127);          // cols 512,513 -> zero
    const bool  bok   = (phb != 127);          // rows ih0+4, ih0+5 valid?
    const float* hi03 = redge ? g_zpad : (base + 4);   // rows 0-3, cols {4,5}
    const float* lo45 = bok   ? base   : g_zpad;       // rows 4-5, cols {0..3}
    const float* hi45 = (bok && !redge) ? (base + 4) : g_zpad;

    // acc[oc][conv_row][tile]: tile t covers conv cols {4t.. } -> {iw0+2t*2, +1}
    ull acc[OCG][4][2];
#pragma unroll
    for (int o = 0; o < OCG; o++)
#pragma unroll
        for (int r = 0; r < 4; r++) { acc[o][r][0] = 0ull; acc[o][r][1] = 0ull; }

#pragma unroll
    for (int ic = 0; ic < ICN; ic++) {
        // 6x6 patch as 5 overlapping column pairs per row:
        // p[rr][j] = {col j, col j+1}, j=0..4. Aligned pairs load as ull;
        // the two straddling pairs are built with midpair.
        ull p[6][5];
#pragma unroll
        for (int rr = 0; rr < 6; rr++) {
            const float* lp = (rr < 4) ? base : lo45;
            const float* hp = (rr < 4) ? hi03 : hi45;
            const ull L0 = *(const ull*)(lp + ic * CH + rr * IW);      // {0,1}
            const ull L1 = *(const ull*)(lp + ic * CH + rr * IW + 2);  // {2,3}
            const ull L2 = *(const ull*)(hp + ic * CH + rr * IW);      // {4,5}
            p[rr][0] = L0;
            p[rr][1] = midpair(L0, L1);
            p[rr][2] = L1;
            p[rr][3] = midpair(L1, L2);
            p[rr][4] = L2;
        }

#pragma unroll
        for (int oc = 0; oc < OCG; oc++) {
            const ull* wp = &c_p.w2[((ocbase + oc) * ICN + ic) * 9];
#pragma unroll
            for (int kh = 0; kh < 3; kh++) {
#pragma unroll
                for (int kw = 0; kw < 3; kw++) {
                    const ull w2 = wp[kh * 3 + kw];   // 1 LDC -> 8 FFMA2
#pragma unroll
                    for (int r = 0; r < 4; r++) {
                        fma2(acc[oc][r][0], p[kh + r][kw],     w2);
                        fma2(acc[oc][r][1], p[kh + r][kw + 2], w2);
                    }
                }
            }
        }
    }

    // Epilogue: (y + bias)*scale -> 2x2 max -> clamp[0,1].
    // Thread owns pooled cols {2tid, 2tid+1}; pack both into one STG.64.
    const int ph0 = phb * 2;
#pragma unroll
    for (int oc = 0; oc < OCG; oc++) {
        const ull sc = c_p.sc[ocbase + oc];
        const ull bs = c_p.bs[ocbase + oc];
        float* orow = out + (((size_t)(bi * OCN + ocbase + oc)) * PH + ph0) * PW + 2 * tid;
#pragma unroll
        for (int pr = 0; pr < 2; pr++) {
            float m[2];
#pragma unroll
            for (int t = 0; t < 2; t++) {
                float e0, e1, e2, e3;
                ull y0 = fma2n(acc[oc][2 * pr + 0][t], sc, bs);
                ull y1 = fma2n(acc[oc][2 * pr + 1][t], sc, bs);
                unpack2(y0, e0, e1);
                unpack2(y1, e2, e3);
                m[t] = fminf(fmaxf(fmaxf(fmaxf(e0, e1), fmaxf(e2, e3)), 0.0f), 1.0f);
            }
            *(ull*)(orow + (size_t)pr * PW) = pack2(m[0], m[1]);
        }
    }
}

extern "C" void kernel_launch(void* const* d_in, const int* in_sizes, int n_in,
                              void* d_out, int out_size) {
    const float* x     = (const float*)d_in[0];
    const float* w     = (const float*)d_in[1];
    const float* bias  = (const float*)d_in[2];
    const float* scale = (const float*)d_in[3];
    float* out = (float*)d_out;

    const int B = in_sizes[0] / (ICN * IH * IW);   // 32

    prep_kernel<<<1, 512>>>(w, bias, scale);

    void* stage_ptr = nullptr;
    cudaGetSymbolAddress(&stage_ptr, g_stage);
    cudaMemcpyToSymbolAsync(c_p, stage_ptr, sizeof(Params), 0,
                            cudaMemcpyDeviceToDevice, 0);

    dim3 block(128);
    dim3 grid(OCN / OCG, PH / 2, B);   // x: 8 oc groups, y: pooled-row pair, z: batch
    conv_pool_clamp_kernel<<<grid, block>>>(x, out);
}

// round 10
// speedup vs baseline: 1.0298x; 1.0002x over previous
#include <cuda_runtime.h>
#include <cstdint>

// Fused: conv3x3 (zero-pad bottom/right) -> +bias -> *scale -> maxpool2x2 -> clamp[0,1]
// x: [B,3,512,512] f32, w: [16,3,3,3], bias: [16], scale: [16,1,1]
// out: [B,16,256,256] f32
//
// R9: thread tile widened to 4 output cols (2 pooled cols) x 4 conv rows x 2 OC.
// Each constant weight load now feeds 8 FFMA2 (was 4) -> the 108-load weight
// stream (R8's hidden co-binder, LDC floor 8) halves to 54. LDG per output /4.
// Coalesced STG.64 epilogue. Weights {w,w} in __constant__ via prep kernel.

typedef unsigned long long ull;

#define OCN 16
#define OCG 2
#define ICN 3
#define IH 512
#define IW 512
#define PH 256
#define PW 256
#define CH (IH * IW)
#define NW (OCN * ICN * 9)   // 432 weight taps

struct Params {
    ull w2[NW];    // {w, w}
    ull sc[OCN];   // {s, s}
    ull bs[OCN];   // {b*s, b*s}
};

__device__    Params g_stage;   // written by prep kernel
__constant__  Params c_p;       // copied from g_stage (D2D memcpy node)

// Zero-filled pad source for bottom/right edges; offsets go up to 2*CH+5*IW+6.
__device__ float g_zpad[2 * CH + 6 * IW + 8];

__device__ __forceinline__ ull pack2(float a, float b) {
    ull r;
    asm("mov.b64 %0, {%1, %2};" : "=l"(r) : "f"(a), "f"(b));
    return r;
}
__device__ __forceinline__ void unpack2(ull p, float& a, float& b) {
    asm("mov.b64 {%0, %1}, %2;" : "=f"(a), "=f"(b) : "l"(p));
}
// {hi(lo-pair), lo(hi-pair)} — straddling middle column pair.
__device__ __forceinline__ ull midpair(ull lo, ull hi) {
    ull r;
    asm("{\n\t"
        ".reg .b32 a, b, c, d;\n\t"
        "mov.b64 {a, b}, %1;\n\t"
        "mov.b64 {c, d}, %2;\n\t"
        "mov.b64 %0, {b, c};\n\t"
        "}" : "=l"(r) : "l"(lo), "l"(hi));
    return r;
}
__device__ __forceinline__ void fma2(ull& acc, ull a, ull b) {
    asm("fma.rn.f32x2 %0, %1, %2, %0;" : "+l"(acc) : "l"(a), "l"(b));
}
__device__ __forceinline__ ull fma2n(ull a, ull b, ull c) {
    ull d;
    asm("fma.rn.f32x2 %0, %1, %2, %3;" : "=l"(d) : "l"(a), "l"(b), "l"(c));
    return d;
}

__global__ void prep_kernel(const float* __restrict__ w,
                            const float* __restrict__ bias,
                            const float* __restrict__ scale) {
    const int i = threadIdx.x;
    if (i < NW) {
        float v = w[i];
        g_stage.w2[i] = pack2(v, v);
    }
    if (i < OCN) {
        float s  = scale[i];
        float bs = bias[i] * s;
        g_stage.sc[i] = pack2(s, s);
        g_stage.bs[i] = pack2(bs, bs);
    }
}

__global__ __launch_bounds__(128, 5)
void conv_pool_clamp_kernel(const float* __restrict__ x,
                            float* __restrict__ out) {
    const int tid = threadIdx.x;              // 0..127: pooled cols {2t, 2t+1}
    const int ocbase = blockIdx.x * OCG;      // 0,2,..,14
    const int phb = blockIdx.y;               // 0..127: pooled-row pair
    const int bi  = blockIdx.z;

    const int ih0 = phb * 4;                  // 6-row input patch start
    const int iw0 = tid * 4;                  // 6-col input patch start

    // Base pointers (all loads are base + compile-time imm). Edge handling via
    // base select into the static zero array -> no per-load predication.
    const float* base = x + (size_t)bi * (ICN * CH) + ih0 * IW + iw0;
    const bool  redge = (tid == 127);          // cols 512,513 -> zero
    const bool  bok   = (phb != 127);          // rows ih0+4, ih0+5 valid?
    const float* hi03 = redge ? g_zpad : (base + 4);   // rows 0-3, cols {4,5}
    const float* lo45 = bok   ? base   : g_zpad;       // rows 4-5, cols {0..3}
    const float* hi45 = (bok && !redge) ? (base + 4) : g_zpad;

    // acc[oc][conv_row][tile]: tile t covers conv cols {4t.. } -> {iw0+2t*2, +1}
    ull acc[OCG][4][2];
#pragma unroll
    for (int o = 0; o < OCG; o++)
#pragma unroll
        for (int r = 0; r < 4; r++) { acc[o][r][0] = 0ull; acc[o][r][1] = 0ull; }

#pragma unroll
    for (int ic = 0; ic < ICN; ic++) {
        // 6x6 patch as 5 overlapping column pairs per row:
        // p[rr][j] = {col j, col j+1}, j=0..4. Aligned pairs load as ull;
        // the two straddling pairs are built with midpair.
        ull p[6][5];
#pragma unroll
        for (int rr = 0; rr < 6; rr++) {
            const float* lp = (rr < 4) ? base : lo45;
            const float* hp = (rr < 4) ? hi03 : hi45;
            const ull L0 = *(const ull*)(lp + ic * CH + rr * IW);      // {0,1}
            const ull L1 = *(const ull*)(lp + ic * CH + rr * IW + 2);  // {2,3}
            const ull L2 = *(const ull*)(hp + ic * CH + rr * IW);      // {4,5}
            p[rr][0] = L0;
            p[rr][1] = midpair(L0, L1);
            p[rr][2] = L1;
            p[rr][3] = midpair(L1, L2);
            p[rr][4] = L2;
        }

#pragma unroll
        for (int oc = 0; oc < OCG; oc++) {
            const ull* wp = &c_p.w2[((ocbase + oc) * ICN + ic) * 9];
#pragma unroll
            for (int kh = 0; kh < 3; kh++) {
#pragma unroll
                for (int kw = 0; kw < 3; kw++) {
                    const ull w2 = wp[kh * 3 + kw];   // 1 LDC -> 8 FFMA2
#pragma unroll
                    for (int r = 0; r < 4; r++) {
                        fma2(acc[oc][r][0], p[kh + r][kw],     w2);
                        fma2(acc[oc][r][1], p[kh + r][kw + 2], w2);
                    }
                }
            }
        }
    }

    // Epilogue: (y + bias)*scale -> 2x2 max -> clamp[0,1].
    // Thread owns pooled cols {2tid, 2tid+1}; pack both into one STG.64.
    const int ph0 = phb * 2;
#pragma unroll
    for (int oc = 0; oc < OCG; oc++) {
        const ull sc = c_p.sc[ocbase + oc];
        const ull bs = c_p.bs[ocbase + oc];
        float* orow = out + (((size_t)(bi * OCN + ocbase + oc)) * PH + ph0) * PW + 2 * tid;
#pragma unroll
        for (int pr = 0; pr < 2; pr++) {
            float m[2];
#pragma unroll
            for (int t = 0; t < 2; t++) {
                float e0, e1, e2, e3;
                ull y0 = fma2n(acc[oc][2 * pr + 0][t], sc, bs);
                ull y1 = fma2n(acc[oc][2 * pr + 1][t], sc, bs);
                unpack2(y0, e0, e1);
                unpack2(y1, e2, e3);
                m[t] = fminf(fmaxf(fmaxf(fmaxf(e0, e1), fmaxf(e2, e3)), 0.0f), 1.0f);
            }
            *(ull*)(orow + (size_t)pr * PW) = pack2(m[0], m[1]);
        }
    }
}

extern "C" void kernel_launch(void* const* d_in, const int* in_sizes, int n_in,
                              void* d_out, int out_size) {
    const float* x     = (const float*)d_in[0];
    const float* w     = (const float*)d_in[1];
    const float* bias  = (const float*)d_in[2];
    const float* scale = (const float*)d_in[3];
    float* out = (float*)d_out;

    const int B = in_sizes[0] / (ICN * IH * IW);   // 32

    prep_kernel<<<1, 512>>>(w, bias, scale);

    void* stage_ptr = nullptr;
    cudaGetSymbolAddress(&stage_ptr, g_stage);
    cudaMemcpyToSymbolAsync(c_p, stage_ptr, sizeof(Params), 0,
                            cudaMemcpyDeviceToDevice, 0);

    dim3 block(128);
    dim3 grid(OCN / OCG, PH / 2, B);   // x: 8 oc groups, y: pooled-row pair, z: batch
    conv_pool_clamp_kernel<<<grid, block>>>(x, out);
}